// round 8
// baseline (speedup 1.0000x reference)
#include <cuda_runtime.h>
#include <cuda_bf16.h>
#include <cuda_fp16.h>
#include <cstdint>
#include <float.h>

#define FEAT 128
#define MAXN 50000
#define MAXE 600000
#define CAP 96

// ---------------- scratch -------------------------------------------------
__device__ __half         g_Ch[MAXN * FEAT];      // theta(x) fp16 (gather reads)
__device__ float          g_D[MAXN * FEAT];       // phi - theta + (tb+pb), fp32
__device__ __nv_bfloat16  g_Xh[MAXN * FEAT];      // hi part of current X
__device__ __nv_bfloat16  g_Xl[MAXN * FEAT];      // lo part of current X
__device__ __nv_bfloat16  g_W2[4 * 256 * 256];    // [l][row<128:theta else phi][k<128:hi else lo]
__device__ int g_cur[MAXN];                       // bucket fill count == degree
__device__ int g_csr[MAXN * CAP];                 // src indices bucketed by dst

// ---------------- fused setup: zero counters + decompose X and W -----------
__global__ void setup_kernel(const float* __restrict__ x,
                             const float* __restrict__ tw,
                             const float* __restrict__ pw, int n) {
    int i = blockIdx.x * blockDim.x + threadIdx.x;
    if (i < n) g_cur[i] = 0;
    if (i < 4 * 256 * 256) {
        int l = i >> 16;
        int r = (i >> 8) & 255;
        int k = i & 255;
        const float* W = (r < 128) ? tw : pw;
        float w = W[(size_t)l * FEAT * FEAT + (size_t)(r & 127) * FEAT + (k & 127)];
        __nv_bfloat16 h = __float2bfloat16(w);
        g_W2[i] = (k < 128) ? h : __float2bfloat16(w - __bfloat162float(h));
    }
    if (i < n * FEAT) {
        float v = x[i];
        __nv_bfloat16 h = __float2bfloat16(v);
        g_Xh[i] = h;
        g_Xl[i] = __float2bfloat16(v - __bfloat162float(h));
    }
}

// ---------------- bucket scatter (no hist/scan needed) ---------------------
__global__ void scatter_kernel(const int* __restrict__ src,
                               const int* __restrict__ dst, int e) {
    int i = blockIdx.x * blockDim.x + threadIdx.x;
    if (i < e) {
        int d = dst[i];
        int p = atomicAdd(&g_cur[d], 1);
        g_csr[d * CAP + p] = src[i];
    }
}

// ---------------- mma.sync GEMM, cp.async 3-stage pipeline -------------------
#define NKC 12
#define STAGE_BYTES 30720
#define STAGE_B_OFF 10240
#define GEMM_SMEM (3 * STAGE_BYTES)

__device__ __forceinline__ uint32_t smem_u32(const void* p) {
    uint32_t a;
    asm("{ .reg .u64 t; cvta.to.shared.u64 t, %1; cvt.u32.u64 %0, t; }" : "=r"(a) : "l"(p));
    return a;
}
__device__ __forceinline__ uint64_t gmem_u64(const void* p) {
    uint64_t a;
    asm("cvta.to.global.u64 %0, %1;" : "=l"(a) : "l"(p));
    return a;
}
#define CP_ASYNC16(dst, src, sz)                                             \
    asm volatile("cp.async.cg.shared.global [%0], [%1], 16, %2;"             \
                 :: "r"(dst), "l"(src), "r"(sz) : "memory")
#define CP_COMMIT() asm volatile("cp.async.commit_group;" ::: "memory")
#define CP_WAIT1() asm volatile("cp.async.wait_group 1;" ::: "memory")
#define CP_WAIT0() asm volatile("cp.async.wait_group 0;" ::: "memory")

#define LDMX4(r0, r1, r2, r3, addr)                                          \
    asm volatile("ldmatrix.sync.aligned.m8n8.x4.shared.b16 {%0,%1,%2,%3}, [%4];" \
                 : "=r"(r0), "=r"(r1), "=r"(r2), "=r"(r3) : "r"(addr))
#define MMA16816(d, a0, a1, a2, a3, b0, b1)                                  \
    asm volatile("mma.sync.aligned.m16n8k16.row.col.f32.bf16.bf16.f32 "      \
                 "{%0,%1,%2,%3},{%4,%5,%6,%7},{%8,%9},{%0,%1,%2,%3};"        \
                 : "+f"((d)[0]), "+f"((d)[1]), "+f"((d)[2]), "+f"((d)[3])    \
                 : "r"(a0), "r"(a1), "r"(a2), "r"(a3), "r"(b0), "r"(b1))

__global__ void __launch_bounds__(512, 1)
gemm_mma_kernel(int layer, const float* __restrict__ tb,
                const float* __restrict__ pb, int n) {
    extern __shared__ __nv_bfloat16 sm[];
    uint32_t smb = smem_u32(sm);
    int t = threadIdx.x, lane = t & 31, wid = t >> 5;
    int m0 = blockIdx.x * 128;

    uint64_t Wg  = gmem_u64(g_W2 + (size_t)layer * 65536);
    uint64_t Xhg = gmem_u64(g_Xh);
    uint64_t Xlg = gmem_u64(g_Xl);

    int warp_m = wid & 3;
    int warp_n = wid >> 2;

    int arow = t >> 2, aq = t & 3;
    int gr = m0 + arow;
    uint32_t a_ok = (gr < n) ? 16u : 0u;
    uint32_t a_dst_off = (uint32_t)(arow * 80 + aq * 16);
    uint64_t a_src_off = ((uint64_t)(uint32_t)gr * FEAT + aq * 8) * 2;
    int i0 = t, i1 = t + 512;
    uint32_t b_dst0 = (uint32_t)(STAGE_B_OFF + (i0 >> 2) * 80 + (i0 & 3) * 16);
    uint32_t b_dst1 = (uint32_t)(STAGE_B_OFF + (i1 >> 2) * 80 + (i1 & 3) * 16);
    uint64_t b_src0 = ((uint64_t)(i0 >> 2) * 256 + (i0 & 3) * 8) * 2;
    uint64_t b_src1 = ((uint64_t)(i1 >> 2) * 256 + (i1 & 3) * 8) * 2;

    auto issue = [&](int kc) {
        int seg = kc >> 2, kcol = (kc & 3) * 32;
        uint32_t st = smb + (uint32_t)(kc % 3) * STAGE_BYTES;
        uint64_t xg = ((seg < 2) ? Xhg : Xlg) + a_src_off + (uint64_t)kcol * 2;
        CP_ASYNC16(st + a_dst_off, xg, a_ok);
        uint64_t bcol2 = (uint64_t)(kcol + ((seg == 1) ? 128 : 0)) * 2;
        CP_ASYNC16(st + b_dst0, Wg + b_src0 + bcol2, 16u);
        CP_ASYNC16(st + b_dst1, Wg + b_src1 + bcol2, 16u);
        CP_COMMIT();
    };

    issue(0);
    issue(1);

    float accT[2][4][4], accP[2][4][4];
    #pragma unroll
    for (int mt = 0; mt < 2; mt++)
        #pragma unroll
        for (int nt = 0; nt < 4; nt++)
            #pragma unroll
            for (int r = 0; r < 4; r++) { accT[mt][nt][r] = 0.f; accP[mt][nt][r] = 0.f; }

    int lr  = (lane & 7) + ((lane >> 3) & 1) * 8;
    int lk8 = (lane >> 4) * 8;
    int bg  = lane >> 3;
    int br_ = (lane & 7) + ((bg >> 1) & 1) * 8;
    int bk8 = (bg & 1) * 8;

    for (int kc = 0; kc < NKC; kc++) {
        if (kc < NKC - 1) { CP_WAIT1(); } else { CP_WAIT0(); }
        __syncthreads();

        uint32_t stA = smb + (uint32_t)(kc % 3) * STAGE_BYTES;
        uint32_t stB = stA + STAGE_B_OFF;

        #pragma unroll
        for (int ks = 0; ks < 2; ks++) {
            int k = ks * 16;
            uint32_t aF[2][4];
            #pragma unroll
            for (int mt = 0; mt < 2; mt++) {
                uint32_t ad = stA + (uint32_t)((warp_m * 32 + mt * 16 + lr) * 80 + (k + lk8) * 2);
                LDMX4(aF[mt][0], aF[mt][1], aF[mt][2], aF[mt][3], ad);
            }
            {
                uint32_t bt[4][2];
                #pragma unroll
                for (int nh = 0; nh < 2; nh++) {
                    uint32_t bd = stB + (uint32_t)((warp_n * 32 + nh * 16 + br_) * 80 + (k + bk8) * 2);
                    LDMX4(bt[nh * 2][0], bt[nh * 2][1], bt[nh * 2 + 1][0], bt[nh * 2 + 1][1], bd);
                }
                #pragma unroll
                for (int mt = 0; mt < 2; mt++)
                    #pragma unroll
                    for (int nt = 0; nt < 4; nt++)
                        MMA16816(accT[mt][nt], aF[mt][0], aF[mt][1], aF[mt][2], aF[mt][3],
                                 bt[nt][0], bt[nt][1]);
            }
            {
                uint32_t bp[4][2];
                #pragma unroll
                for (int nh = 0; nh < 2; nh++) {
                    uint32_t bd = stB + (uint32_t)((128 + warp_n * 32 + nh * 16 + br_) * 80 + (k + bk8) * 2);
                    LDMX4(bp[nh * 2][0], bp[nh * 2][1], bp[nh * 2 + 1][0], bp[nh * 2 + 1][1], bd);
                }
                #pragma unroll
                for (int mt = 0; mt < 2; mt++)
                    #pragma unroll
                    for (int nt = 0; nt < 4; nt++)
                        MMA16816(accP[mt][nt], aF[mt][0], aF[mt][1], aF[mt][2], aF[mt][3],
                                 bp[nt][0], bp[nt][1]);
            }
        }

        if (kc + 2 < NKC) issue(kc + 2);
    }

    // epilogue: g_Ch = fp16(theta); g_D = phi - theta + (tb+pb)
    #pragma unroll
    for (int mt = 0; mt < 2; mt++) {
        #pragma unroll
        for (int nt = 0; nt < 4; nt++) {
            int f = warp_n * 32 + nt * 8 + (lane & 3) * 2;
            float bias0 = __ldg(&tb[f]) + __ldg(&pb[f]);
            float bias1 = __ldg(&tb[f + 1]) + __ldg(&pb[f + 1]);
            int m = m0 + warp_m * 32 + mt * 16 + (lane >> 2);
            float* c = accT[mt][nt];
            float* p = accP[mt][nt];
            if (m < n) {
                *(__half2*)(g_Ch + (size_t)m * FEAT + f) = __floats2half2_rn(c[0], c[1]);
                *(float2*)(g_D + (size_t)m * FEAT + f) =
                    make_float2(p[0] - c[0] + bias0, p[1] - c[1] + bias1);
            }
            if (m + 8 < n) {
                *(__half2*)(g_Ch + (size_t)(m + 8) * FEAT + f) = __floats2half2_rn(c[2], c[3]);
                *(float2*)(g_D + (size_t)(m + 8) * FEAT + f) =
                    make_float2(p[2] - c[2] + bias0, p[3] - c[3] + bias1);
            }
        }
    }
}

// ---------------- gather-max: 2 warps per node, MLP=2 each, smem merge -----
__device__ __forceinline__ uint32_t hmax2u(uint32_t x, uint32_t y) {
    __half2 r = __hmax2(*(__half2*)&x, *(__half2*)&y);
    return *(uint32_t*)&r;
}

__global__ void gather_kernel(float* __restrict__ dout, int layer, int n) {
    __shared__ uint32_t part[2][8][32];
    int lane = threadIdx.x & 31, wib = threadIdx.x >> 5;   // 8 warps/block
    int gwarp = blockIdx.x * 8 + wib;
    int node = gwarp >> 1;
    int sub = wib & 1;            // which half of the edge list

    const uint32_t NEG = 0xFBFFFBFFu;  // -65504 x2
    uint32_t a0 = NEG, a1 = NEG, b0 = NEG, b1 = NEG;

    if (node < n) {
        int deg = g_cur[node];
        const int* lst = g_csr + node * CAP;
        const uint2* C2 = (const uint2*)g_Ch;
        int e = sub;
        for (; e + 2 < deg; e += 4) {      // MLP=2 per warp, edges e and e+2
            int s0 = __ldg(&lst[e]);
            int s1 = __ldg(&lst[e + 2]);
            uint2 v0 = __ldg(&C2[(size_t)s0 * 32 + lane]);
            uint2 v1 = __ldg(&C2[(size_t)s1 * 32 + lane]);
            a0 = hmax2u(a0, v0.x); a1 = hmax2u(a1, v0.y);
            b0 = hmax2u(b0, v1.x); b1 = hmax2u(b1, v1.y);
        }
        if (e < deg) {
            int s0 = __ldg(&lst[e]);
            uint2 v0 = __ldg(&C2[(size_t)s0 * 32 + lane]);
            a0 = hmax2u(a0, v0.x); a1 = hmax2u(a1, v0.y);
        }
        a0 = hmax2u(a0, b0);
        a1 = hmax2u(a1, b1);
    }
    part[0][wib][lane] = a0;
    part[1][wib][lane] = a1;
    __syncthreads();

    if (sub == 0 && node < n) {
        a0 = hmax2u(a0, part[0][wib + 1][lane]);
        a1 = hmax2u(a1, part[1][wib + 1][lane]);

        float2 m01 = __half22float2(*(__half2*)&a0);
        float2 m23 = __half22float2(*(__half2*)&a1);

        float4 d = __ldg(&((const float4*)g_D)[(size_t)node * 32 + lane]);
        float4 o;
        o.x = fmaxf(0.f, d.x + m01.x);
        o.y = fmaxf(0.f, d.y + m01.y);
        o.z = fmaxf(0.f, d.z + m23.x);
        o.w = fmaxf(0.f, d.w + m23.y);

        if (layer == 3) {
            ((float4*)dout)[(size_t)node * 32 + lane] = o;
        } else {
            __nv_bfloat16 h0 = __float2bfloat16(o.x), h1 = __float2bfloat16(o.y);
            __nv_bfloat16 h2 = __float2bfloat16(o.z), h3 = __float2bfloat16(o.w);
            __nv_bfloat162 hp0(h0, h1), hp1(h2, h3);
            __nv_bfloat162 lp0(
                __float2bfloat16(o.x - __bfloat162float(h0)),
                __float2bfloat16(o.y - __bfloat162float(h1)));
            __nv_bfloat162 lp1(
                __float2bfloat16(o.z - __bfloat162float(h2)),
                __float2bfloat16(o.w - __bfloat162float(h3)));
            uint2 hv, lv;
            hv.x = *(uint32_t*)&hp0; hv.y = *(uint32_t*)&hp1;
            lv.x = *(uint32_t*)&lp0; lv.y = *(uint32_t*)&lp1;
            *(uint2*)(g_Xh + (size_t)node * FEAT + lane * 4) = hv;
            *(uint2*)(g_Xl + (size_t)node * FEAT + lane * 4) = lv;
        }
    }
}

// ---------------- launch ----------------------------------------------------
extern "C" void kernel_launch(void* const* d_in, const int* in_sizes, int n_in,
                              void* d_out, int out_size) {
    const float* feats = (const float*)d_in[0];
    const int*   src   = (const int*)d_in[1];
    const int*   dst   = (const int*)d_in[2];
    const float* tw    = (const float*)d_in[3];
    const float* tb    = (const float*)d_in[4];
    const float* pw    = (const float*)d_in[5];
    const float* pb    = (const float*)d_in[6];

    int n = in_sizes[0] / FEAT;
    int e = in_sizes[1];
    if (n > MAXN) n = MAXN;
    if (e > MAXE) e = MAXE;

    static int smem_set = 0;
    if (!smem_set) {
        cudaFuncSetAttribute(gemm_mma_kernel,
                             cudaFuncAttributeMaxDynamicSharedMemorySize, GEMM_SMEM);
        smem_set = 1;
    }

    setup_kernel<<<(n * FEAT + 255) / 256, 256>>>(feats, tw, pw, n);
    scatter_kernel<<<(e + 255) / 256, 256>>>(src, dst, e);

    int gemm_gx = (n + 127) / 128;
    int gather_blocks = (n + 3) / 4;   // 2 warps per node, 8 warps per block

    for (int l = 0; l < 4; l++) {
        gemm_mma_kernel<<<gemm_gx, 512, GEMM_SMEM>>>(l, tb + l * FEAT, pb + l * FEAT, n);
        gather_kernel<<<gather_blocks, 256>>>((float*)d_out, l, n);
    }
}

// round 9
// speedup vs baseline: 1.1444x; 1.1444x over previous
#include <cuda_runtime.h>
#include <cuda_bf16.h>
#include <cuda_fp16.h>
#include <cstdint>
#include <float.h>

#define FEAT 128
#define MAXN 50000
#define MAXE 600000
#define CAP 96

// ---------------- scratch -------------------------------------------------
__device__ __half         g_Ch[MAXN * FEAT];      // theta(x) fp16 (gather reads)
__device__ __half         g_Dh[MAXN * FEAT];      // phi - theta + (tb+pb), fp16
__device__ __nv_bfloat16  g_Xh[MAXN * FEAT];      // hi part of current X
__device__ __nv_bfloat16  g_Xl[MAXN * FEAT];      // lo part of current X
__device__ __nv_bfloat16  g_W2[4 * 256 * 256];    // [l][row<128:theta else phi][k<128:hi else lo]
__device__ int g_cur[MAXN];                       // bucket fill count == degree
__device__ int g_csr[MAXN * CAP];                 // src indices bucketed by dst

// ---------------- fused setup: zero counters + decompose X and W -----------
__global__ void setup_kernel(const float* __restrict__ x,
                             const float* __restrict__ tw,
                             const float* __restrict__ pw, int n) {
    int i = blockIdx.x * blockDim.x + threadIdx.x;
    if (i < n) g_cur[i] = 0;
    if (i < 4 * 256 * 256) {
        int l = i >> 16;
        int r = (i >> 8) & 255;
        int k = i & 255;
        const float* W = (r < 128) ? tw : pw;
        float w = W[(size_t)l * FEAT * FEAT + (size_t)(r & 127) * FEAT + (k & 127)];
        __nv_bfloat16 h = __float2bfloat16(w);
        g_W2[i] = (k < 128) ? h : __float2bfloat16(w - __bfloat162float(h));
    }
    if (i < n * FEAT) {
        float v = x[i];
        __nv_bfloat16 h = __float2bfloat16(v);
        g_Xh[i] = h;
        g_Xl[i] = __float2bfloat16(v - __bfloat162float(h));
    }
}

// ---------------- bucket scatter (no hist/scan needed) ---------------------
__global__ void scatter_kernel(const int* __restrict__ src,
                               const int* __restrict__ dst, int e) {
    int i = blockIdx.x * blockDim.x + threadIdx.x;
    if (i < e) {
        int d = dst[i];
        int p = atomicAdd(&g_cur[d], 1);
        g_csr[d * CAP + p] = src[i];
    }
}

// ---------------- mma.sync GEMM, cp.async 3-stage pipeline -------------------
#define NKC 12
#define STAGE_BYTES 30720
#define STAGE_B_OFF 10240
#define GEMM_SMEM (3 * STAGE_BYTES)

__device__ __forceinline__ uint32_t smem_u32(const void* p) {
    uint32_t a;
    asm("{ .reg .u64 t; cvta.to.shared.u64 t, %1; cvt.u32.u64 %0, t; }" : "=r"(a) : "l"(p));
    return a;
}
__device__ __forceinline__ uint64_t gmem_u64(const void* p) {
    uint64_t a;
    asm("cvta.to.global.u64 %0, %1;" : "=l"(a) : "l"(p));
    return a;
}
#define CP_ASYNC16(dst, src, sz)                                             \
    asm volatile("cp.async.cg.shared.global [%0], [%1], 16, %2;"             \
                 :: "r"(dst), "l"(src), "r"(sz) : "memory")
#define CP_COMMIT() asm volatile("cp.async.commit_group;" ::: "memory")
#define CP_WAIT1() asm volatile("cp.async.wait_group 1;" ::: "memory")
#define CP_WAIT0() asm volatile("cp.async.wait_group 0;" ::: "memory")

#define LDMX4(r0, r1, r2, r3, addr)                                          \
    asm volatile("ldmatrix.sync.aligned.m8n8.x4.shared.b16 {%0,%1,%2,%3}, [%4];" \
                 : "=r"(r0), "=r"(r1), "=r"(r2), "=r"(r3) : "r"(addr))
#define MMA16816(d, a0, a1, a2, a3, b0, b1)                                  \
    asm volatile("mma.sync.aligned.m16n8k16.row.col.f32.bf16.bf16.f32 "      \
                 "{%0,%1,%2,%3},{%4,%5,%6,%7},{%8,%9},{%0,%1,%2,%3};"        \
                 : "+f"((d)[0]), "+f"((d)[1]), "+f"((d)[2]), "+f"((d)[3])    \
                 : "r"(a0), "r"(a1), "r"(a2), "r"(a3), "r"(b0), "r"(b1))

__global__ void __launch_bounds__(512, 1)
gemm_mma_kernel(int layer, const float* __restrict__ tb,
                const float* __restrict__ pb, int n) {
    extern __shared__ __nv_bfloat16 sm[];
    uint32_t smb = smem_u32(sm);
    int t = threadIdx.x, lane = t & 31, wid = t >> 5;
    int m0 = blockIdx.x * 128;

    uint64_t Wg  = gmem_u64(g_W2 + (size_t)layer * 65536);
    uint64_t Xhg = gmem_u64(g_Xh);
    uint64_t Xlg = gmem_u64(g_Xl);

    int warp_m = wid & 3;
    int warp_n = wid >> 2;

    int arow = t >> 2, aq = t & 3;
    int gr = m0 + arow;
    uint32_t a_ok = (gr < n) ? 16u : 0u;
    uint32_t a_dst_off = (uint32_t)(arow * 80 + aq * 16);
    uint64_t a_src_off = ((uint64_t)(uint32_t)gr * FEAT + aq * 8) * 2;
    int i0 = t, i1 = t + 512;
    uint32_t b_dst0 = (uint32_t)(STAGE_B_OFF + (i0 >> 2) * 80 + (i0 & 3) * 16);
    uint32_t b_dst1 = (uint32_t)(STAGE_B_OFF + (i1 >> 2) * 80 + (i1 & 3) * 16);
    uint64_t b_src0 = ((uint64_t)(i0 >> 2) * 256 + (i0 & 3) * 8) * 2;
    uint64_t b_src1 = ((uint64_t)(i1 >> 2) * 256 + (i1 & 3) * 8) * 2;

    auto issue = [&](int kc) {
        int seg = kc >> 2, kcol = (kc & 3) * 32;
        uint32_t st = smb + (uint32_t)(kc % 3) * STAGE_BYTES;
        uint64_t xg = ((seg < 2) ? Xhg : Xlg) + a_src_off + (uint64_t)kcol * 2;
        CP_ASYNC16(st + a_dst_off, xg, a_ok);
        uint64_t bcol2 = (uint64_t)(kcol + ((seg == 1) ? 128 : 0)) * 2;
        CP_ASYNC16(st + b_dst0, Wg + b_src0 + bcol2, 16u);
        CP_ASYNC16(st + b_dst1, Wg + b_src1 + bcol2, 16u);
        CP_COMMIT();
    };

    issue(0);
    issue(1);

    float accT[2][4][4], accP[2][4][4];
    #pragma unroll
    for (int mt = 0; mt < 2; mt++)
        #pragma unroll
        for (int nt = 0; nt < 4; nt++)
            #pragma unroll
            for (int r = 0; r < 4; r++) { accT[mt][nt][r] = 0.f; accP[mt][nt][r] = 0.f; }

    int lr  = (lane & 7) + ((lane >> 3) & 1) * 8;
    int lk8 = (lane >> 4) * 8;
    int bg  = lane >> 3;
    int br_ = (lane & 7) + ((bg >> 1) & 1) * 8;
    int bk8 = (bg & 1) * 8;

    for (int kc = 0; kc < NKC; kc++) {
        if (kc < NKC - 1) { CP_WAIT1(); } else { CP_WAIT0(); }
        __syncthreads();

        uint32_t stA = smb + (uint32_t)(kc % 3) * STAGE_BYTES;
        uint32_t stB = stA + STAGE_B_OFF;

        #pragma unroll
        for (int ks = 0; ks < 2; ks++) {
            int k = ks * 16;
            uint32_t aF[2][4];
            #pragma unroll
            for (int mt = 0; mt < 2; mt++) {
                uint32_t ad = stA + (uint32_t)((warp_m * 32 + mt * 16 + lr) * 80 + (k + lk8) * 2);
                LDMX4(aF[mt][0], aF[mt][1], aF[mt][2], aF[mt][3], ad);
            }
            {
                uint32_t bt[4][2];
                #pragma unroll
                for (int nh = 0; nh < 2; nh++) {
                    uint32_t bd = stB + (uint32_t)((warp_n * 32 + nh * 16 + br_) * 80 + (k + bk8) * 2);
                    LDMX4(bt[nh * 2][0], bt[nh * 2][1], bt[nh * 2 + 1][0], bt[nh * 2 + 1][1], bd);
                }
                #pragma unroll
                for (int mt = 0; mt < 2; mt++)
                    #pragma unroll
                    for (int nt = 0; nt < 4; nt++)
                        MMA16816(accT[mt][nt], aF[mt][0], aF[mt][1], aF[mt][2], aF[mt][3],
                                 bt[nt][0], bt[nt][1]);
            }
            {
                uint32_t bp[4][2];
                #pragma unroll
                for (int nh = 0; nh < 2; nh++) {
                    uint32_t bd = stB + (uint32_t)((128 + warp_n * 32 + nh * 16 + br_) * 80 + (k + bk8) * 2);
                    LDMX4(bp[nh * 2][0], bp[nh * 2][1], bp[nh * 2 + 1][0], bp[nh * 2 + 1][1], bd);
                }
                #pragma unroll
                for (int mt = 0; mt < 2; mt++)
                    #pragma unroll
                    for (int nt = 0; nt < 4; nt++)
                        MMA16816(accP[mt][nt], aF[mt][0], aF[mt][1], aF[mt][2], aF[mt][3],
                                 bp[nt][0], bp[nt][1]);
            }
        }

        if (kc + 2 < NKC) issue(kc + 2);
    }

    // epilogue: g_Ch = fp16(theta); g_Dh = fp16(phi - theta + (tb+pb))
    #pragma unroll
    for (int mt = 0; mt < 2; mt++) {
        #pragma unroll
        for (int nt = 0; nt < 4; nt++) {
            int f = warp_n * 32 + nt * 8 + (lane & 3) * 2;
            float bias0 = __ldg(&tb[f]) + __ldg(&pb[f]);
            float bias1 = __ldg(&tb[f + 1]) + __ldg(&pb[f + 1]);
            int m = m0 + warp_m * 32 + mt * 16 + (lane >> 2);
            float* c = accT[mt][nt];
            float* p = accP[mt][nt];
            if (m < n) {
                *(__half2*)(g_Ch + (size_t)m * FEAT + f) = __floats2half2_rn(c[0], c[1]);
                *(__half2*)(g_Dh + (size_t)m * FEAT + f) =
                    __floats2half2_rn(p[0] - c[0] + bias0, p[1] - c[1] + bias1);
            }
            if (m + 8 < n) {
                *(__half2*)(g_Ch + (size_t)(m + 8) * FEAT + f) = __floats2half2_rn(c[2], c[3]);
                *(__half2*)(g_Dh + (size_t)(m + 8) * FEAT + f) =
                    __floats2half2_rn(p[2] - c[2] + bias0, p[3] - c[3] + bias1);
            }
        }
    }
}

// ---------------- gather-max: R5 shape (1 warp/node, uint2, MLP=2) ---------
__device__ __forceinline__ uint32_t hmax2u(uint32_t x, uint32_t y) {
    __half2 r = __hmax2(*(__half2*)&x, *(__half2*)&y);
    return *(uint32_t*)&r;
}

__global__ void gather_kernel(float* __restrict__ dout, int layer, int n) {
    int gw = (blockIdx.x * blockDim.x + threadIdx.x) >> 5;
    int lane = threadIdx.x & 31;
    if (gw >= n) return;

    int deg = g_cur[gw];
    const int* lst = g_csr + gw * CAP;
    const uint2* C2 = (const uint2*)g_Ch;

    const uint32_t NEG = 0xFBFFFBFFu;  // -65504 x2
    uint32_t a0 = NEG, a1 = NEG, b0 = NEG, b1 = NEG;

    int e = 0;
    for (; e + 1 < deg; e += 2) {
        int s0 = __ldg(&lst[e]);
        int s1 = __ldg(&lst[e + 1]);
        uint2 v0 = __ldg(&C2[(size_t)s0 * 32 + lane]);
        uint2 v1 = __ldg(&C2[(size_t)s1 * 32 + lane]);
        a0 = hmax2u(a0, v0.x); a1 = hmax2u(a1, v0.y);
        b0 = hmax2u(b0, v1.x); b1 = hmax2u(b1, v1.y);
    }
    if (e < deg) {
        int s0 = __ldg(&lst[e]);
        uint2 v0 = __ldg(&C2[(size_t)s0 * 32 + lane]);
        a0 = hmax2u(a0, v0.x); a1 = hmax2u(a1, v0.y);
    }
    a0 = hmax2u(a0, b0);
    a1 = hmax2u(a1, b1);

    float2 m01 = __half22float2(*(__half2*)&a0);
    float2 m23 = __half22float2(*(__half2*)&a1);

    uint2 dv = __ldg(&((const uint2*)g_Dh)[(size_t)gw * 32 + lane]);
    float2 d01 = __half22float2(*(__half2*)&dv.x);
    float2 d23 = __half22float2(*(__half2*)&dv.y);

    float4 o;
    o.x = fmaxf(0.f, d01.x + m01.x);
    o.y = fmaxf(0.f, d01.y + m01.y);
    o.z = fmaxf(0.f, d23.x + m23.x);
    o.w = fmaxf(0.f, d23.y + m23.y);

    if (layer == 3) {
        ((float4*)dout)[(size_t)gw * 32 + lane] = o;
    } else {
        __nv_bfloat16 h0 = __float2bfloat16(o.x), h1 = __float2bfloat16(o.y);
        __nv_bfloat16 h2 = __float2bfloat16(o.z), h3 = __float2bfloat16(o.w);
        __nv_bfloat162 hp0(h0, h1), hp1(h2, h3);
        __nv_bfloat162 lp0(
            __float2bfloat16(o.x - __bfloat162float(h0)),
            __float2bfloat16(o.y - __bfloat162float(h1)));
        __nv_bfloat162 lp1(
            __float2bfloat16(o.z - __bfloat162float(h2)),
            __float2bfloat16(o.w - __bfloat162float(h3)));
        uint2 hv, lv;
        hv.x = *(uint32_t*)&hp0; hv.y = *(uint32_t*)&hp1;
        lv.x = *(uint32_t*)&lp0; lv.y = *(uint32_t*)&lp1;
        *(uint2*)(g_Xh + (size_t)gw * FEAT + lane * 4) = hv;
        *(uint2*)(g_Xl + (size_t)gw * FEAT + lane * 4) = lv;
    }
}

// ---------------- launch ----------------------------------------------------
extern "C" void kernel_launch(void* const* d_in, const int* in_sizes, int n_in,
                              void* d_out, int out_size) {
    const float* feats = (const float*)d_in[0];
    const int*   src   = (const int*)d_in[1];
    const int*   dst   = (const int*)d_in[2];
    const float* tw    = (const float*)d_in[3];
    const float* tb    = (const float*)d_in[4];
    const float* pw    = (const float*)d_in[5];
    const float* pb    = (const float*)d_in[6];

    int n = in_sizes[0] / FEAT;
    int e = in_sizes[1];
    if (n > MAXN) n = MAXN;
    if (e > MAXE) e = MAXE;

    static int smem_set = 0;
    if (!smem_set) {
        cudaFuncSetAttribute(gemm_mma_kernel,
                             cudaFuncAttributeMaxDynamicSharedMemorySize, GEMM_SMEM);
        smem_set = 1;
    }

    setup_kernel<<<(n * FEAT + 255) / 256, 256>>>(feats, tw, pw, n);
    scatter_kernel<<<(e + 255) / 256, 256>>>(src, dst, e);

    int gemm_gx = (n + 127) / 128;
    int warp_blocks = (n * 32 + 255) / 256;

    for (int l = 0; l < 4; l++) {
        gemm_mma_kernel<<<gemm_gx, 512, GEMM_SMEM>>>(l, tb + l * FEAT, pb + l * FEAT, n);
        gather_kernel<<<warp_blocks, 256>>>((float*)d_out, l, n);
    }
}

// round 10
// speedup vs baseline: 1.1902x; 1.0400x over previous
#include <cuda_runtime.h>
#include <cuda_bf16.h>
#include <cuda_fp16.h>
#include <cstdint>
#include <float.h>

#define FEAT 128
#define MAXN 50000
#define MAXE 600000
#define CAP 96

// ---------------- scratch -------------------------------------------------
__device__ __half         g_Ch[MAXN * FEAT];      // theta(x) fp16 (gather reads)
__device__ __half         g_Dh[MAXN * FEAT];      // phi - theta + (tb+pb), fp16
__device__ __nv_bfloat16  g_Xh[MAXN * FEAT];      // hi part of current X
__device__ __nv_bfloat16  g_Xl[MAXN * FEAT];      // lo part of current X
__device__ __nv_bfloat16  g_W2[4 * 256 * 256];    // [l][row<128:theta else phi][k<128:hi else lo]
__device__ int g_cur[MAXN];   // bucket fill count == degree (zero-init at load;
                              // re-zeroed by gather layer 3 for the next run)
__device__ int g_csr[MAXN * CAP];                 // premultiplied src*32, bucketed by dst

// ------- fused setup: decompose X and W + bucket scatter (g_cur already 0) --
__global__ void setup_kernel(const float* __restrict__ x,
                             const float* __restrict__ tw,
                             const float* __restrict__ pw,
                             const int* __restrict__ src,
                             const int* __restrict__ dst,
                             int n, int e) {
    int i = blockIdx.x * blockDim.x + threadIdx.x;
    if (i < e) {
        int d = dst[i];
        int p = atomicAdd(&g_cur[d], 1);
        g_csr[d * CAP + p] = src[i] * 32;   // premultiplied uint2-row index
    }
    if (i < 4 * 256 * 256) {
        int l = i >> 16;
        int r = (i >> 8) & 255;
        int k = i & 255;
        const float* W = (r < 128) ? tw : pw;
        float w = W[(size_t)l * FEAT * FEAT + (size_t)(r & 127) * FEAT + (k & 127)];
        __nv_bfloat16 h = __float2bfloat16(w);
        g_W2[i] = (k < 128) ? h : __float2bfloat16(w - __bfloat162float(h));
    }
    if (i < n * FEAT) {
        float v = x[i];
        __nv_bfloat16 h = __float2bfloat16(v);
        g_Xh[i] = h;
        g_Xl[i] = __float2bfloat16(v - __bfloat162float(h));
    }
}

// ---------------- mma.sync GEMM, cp.async 4-stage pipeline -------------------
#define NKC 12
#define STAGE_BYTES 30720
#define STAGE_B_OFF 10240
#define GEMM_SMEM (4 * STAGE_BYTES)

__device__ __forceinline__ uint32_t smem_u32(const void* p) {
    uint32_t a;
    asm("{ .reg .u64 t; cvta.to.shared.u64 t, %1; cvt.u32.u64 %0, t; }" : "=r"(a) : "l"(p));
    return a;
}
__device__ __forceinline__ uint64_t gmem_u64(const void* p) {
    uint64_t a;
    asm("cvta.to.global.u64 %0, %1;" : "=l"(a) : "l"(p));
    return a;
}
#define CP_ASYNC16(dst, src, sz)                                             \
    asm volatile("cp.async.cg.shared.global [%0], [%1], 16, %2;"             \
                 :: "r"(dst), "l"(src), "r"(sz) : "memory")
#define CP_COMMIT() asm volatile("cp.async.commit_group;" ::: "memory")
#define CP_WAIT2() asm volatile("cp.async.wait_group 2;" ::: "memory")
#define CP_WAIT1() asm volatile("cp.async.wait_group 1;" ::: "memory")
#define CP_WAIT0() asm volatile("cp.async.wait_group 0;" ::: "memory")

#define LDMX4(r0, r1, r2, r3, addr)                                          \
    asm volatile("ldmatrix.sync.aligned.m8n8.x4.shared.b16 {%0,%1,%2,%3}, [%4];" \
                 : "=r"(r0), "=r"(r1), "=r"(r2), "=r"(r3) : "r"(addr))
#define MMA16816(d, a0, a1, a2, a3, b0, b1)                                  \
    asm volatile("mma.sync.aligned.m16n8k16.row.col.f32.bf16.bf16.f32 "      \
                 "{%0,%1,%2,%3},{%4,%5,%6,%7},{%8,%9},{%0,%1,%2,%3};"        \
                 : "+f"((d)[0]), "+f"((d)[1]), "+f"((d)[2]), "+f"((d)[3])    \
                 : "r"(a0), "r"(a1), "r"(a2), "r"(a3), "r"(b0), "r"(b1))

__global__ void __launch_bounds__(512, 1)
gemm_mma_kernel(int layer, const float* __restrict__ tb,
                const float* __restrict__ pb, int n) {
    extern __shared__ __nv_bfloat16 sm[];
    uint32_t smb = smem_u32(sm);
    int t = threadIdx.x, lane = t & 31, wid = t >> 5;
    int m0 = blockIdx.x * 128;

    uint64_t Wg  = gmem_u64(g_W2 + (size_t)layer * 65536);
    uint64_t Xhg = gmem_u64(g_Xh);
    uint64_t Xlg = gmem_u64(g_Xl);

    int warp_m = wid & 3;
    int warp_n = wid >> 2;

    int arow = t >> 2, aq = t & 3;
    int gr = m0 + arow;
    uint32_t a_ok = (gr < n) ? 16u : 0u;
    uint32_t a_dst_off = (uint32_t)(arow * 80 + aq * 16);
    uint64_t a_src_off = ((uint64_t)(uint32_t)gr * FEAT + aq * 8) * 2;
    int i0 = t, i1 = t + 512;
    uint32_t b_dst0 = (uint32_t)(STAGE_B_OFF + (i0 >> 2) * 80 + (i0 & 3) * 16);
    uint32_t b_dst1 = (uint32_t)(STAGE_B_OFF + (i1 >> 2) * 80 + (i1 & 3) * 16);
    uint64_t b_src0 = ((uint64_t)(i0 >> 2) * 256 + (i0 & 3) * 8) * 2;
    uint64_t b_src1 = ((uint64_t)(i1 >> 2) * 256 + (i1 & 3) * 8) * 2;

    auto issue = [&](int kc) {
        int seg = kc >> 2, kcol = (kc & 3) * 32;
        uint32_t st = smb + (uint32_t)(kc & 3) * STAGE_BYTES;
        uint64_t xg = ((seg < 2) ? Xhg : Xlg) + a_src_off + (uint64_t)kcol * 2;
        CP_ASYNC16(st + a_dst_off, xg, a_ok);
        uint64_t bcol2 = (uint64_t)(kcol + ((seg == 1) ? 128 : 0)) * 2;
        CP_ASYNC16(st + b_dst0, Wg + b_src0 + bcol2, 16u);
        CP_ASYNC16(st + b_dst1, Wg + b_src1 + bcol2, 16u);
        CP_COMMIT();
    };

    issue(0);
    issue(1);
    issue(2);

    float accT[2][4][4], accP[2][4][4];
    #pragma unroll
    for (int mt = 0; mt < 2; mt++)
        #pragma unroll
        for (int nt = 0; nt < 4; nt++)
            #pragma unroll
            for (int r = 0; r < 4; r++) { accT[mt][nt][r] = 0.f; accP[mt][nt][r] = 0.f; }

    int lr  = (lane & 7) + ((lane >> 3) & 1) * 8;
    int lk8 = (lane >> 4) * 8;
    int bg  = lane >> 3;
    int br_ = (lane & 7) + ((bg >> 1) & 1) * 8;
    int bk8 = (bg & 1) * 8;

    for (int kc = 0; kc < NKC; kc++) {
        if (kc < NKC - 2) { CP_WAIT2(); }
        else if (kc < NKC - 1) { CP_WAIT1(); }
        else { CP_WAIT0(); }
        __syncthreads();

        uint32_t stA = smb + (uint32_t)(kc & 3) * STAGE_BYTES;
        uint32_t stB = stA + STAGE_B_OFF;

        #pragma unroll
        for (int ks = 0; ks < 2; ks++) {
            int k = ks * 16;
            uint32_t aF[2][4];
            #pragma unroll
            for (int mt = 0; mt < 2; mt++) {
                uint32_t ad = stA + (uint32_t)((warp_m * 32 + mt * 16 + lr) * 80 + (k + lk8) * 2);
                LDMX4(aF[mt][0], aF[mt][1], aF[mt][2], aF[mt][3], ad);
            }
            {
                uint32_t bt[4][2];
                #pragma unroll
                for (int nh = 0; nh < 2; nh++) {
                    uint32_t bd = stB + (uint32_t)((warp_n * 32 + nh * 16 + br_) * 80 + (k + bk8) * 2);
                    LDMX4(bt[nh * 2][0], bt[nh * 2][1], bt[nh * 2 + 1][0], bt[nh * 2 + 1][1], bd);
                }
                #pragma unroll
                for (int mt = 0; mt < 2; mt++)
                    #pragma unroll
                    for (int nt = 0; nt < 4; nt++)
                        MMA16816(accT[mt][nt], aF[mt][0], aF[mt][1], aF[mt][2], aF[mt][3],
                                 bt[nt][0], bt[nt][1]);
            }
            {
                uint32_t bp[4][2];
                #pragma unroll
                for (int nh = 0; nh < 2; nh++) {
                    uint32_t bd = stB + (uint32_t)((128 + warp_n * 32 + nh * 16 + br_) * 80 + (k + bk8) * 2);
                    LDMX4(bp[nh * 2][0], bp[nh * 2][1], bp[nh * 2 + 1][0], bp[nh * 2 + 1][1], bd);
                }
                #pragma unroll
                for (int mt = 0; mt < 2; mt++)
                    #pragma unroll
                    for (int nt = 0; nt < 4; nt++)
                        MMA16816(accP[mt][nt], aF[mt][0], aF[mt][1], aF[mt][2], aF[mt][3],
                                 bp[nt][0], bp[nt][1]);
            }
        }

        if (kc + 3 < NKC) issue(kc + 3);
    }

    // epilogue: g_Ch = fp16(theta); g_Dh = fp16(phi - theta + (tb+pb))
    #pragma unroll
    for (int mt = 0; mt < 2; mt++) {
        #pragma unroll
        for (int nt = 0; nt < 4; nt++) {
            int f = warp_n * 32 + nt * 8 + (lane & 3) * 2;
            float bias0 = __ldg(&tb[f]) + __ldg(&pb[f]);
            float bias1 = __ldg(&tb[f + 1]) + __ldg(&pb[f + 1]);
            int m = m0 + warp_m * 32 + mt * 16 + (lane >> 2);
            float* c = accT[mt][nt];
            float* p = accP[mt][nt];
            if (m < n) {
                *(__half2*)(g_Ch + (size_t)m * FEAT + f) = __floats2half2_rn(c[0], c[1]);
                *(__half2*)(g_Dh + (size_t)m * FEAT + f) =
                    __floats2half2_rn(p[0] - c[0] + bias0, p[1] - c[1] + bias1);
            }
            if (m + 8 < n) {
                *(__half2*)(g_Ch + (size_t)(m + 8) * FEAT + f) = __floats2half2_rn(c[2], c[3]);
                *(__half2*)(g_Dh + (size_t)(m + 8) * FEAT + f) =
                    __floats2half2_rn(p[2] - c[2] + bias0, p[3] - c[3] + bias1);
            }
        }
    }
}

// ---------------- gather-max: 1 warp/node, uint2, MLP=2 --------------------
__device__ __forceinline__ uint32_t hmax2u(uint32_t x, uint32_t y) {
    __half2 r = __hmax2(*(__half2*)&x, *(__half2*)&y);
    return *(uint32_t*)&r;
}

__global__ void gather_kernel(float* __restrict__ dout, int layer, int n) {
    int gw = (blockIdx.x * blockDim.x + threadIdx.x) >> 5;
    int lane = threadIdx.x & 31;
    if (gw >= n) return;

    int deg = g_cur[gw];
    const int* lst = g_csr + gw * CAP;
    const uint2* C2 = (const uint2*)g_Ch;

    // hoisted D load (independent of edge loop)
    uint2 dv = __ldg(&((const uint2*)g_Dh)[(size_t)gw * 32 + lane]);

    const uint32_t NEG = 0xFBFFFBFFu;  // -65504 x2
    uint32_t a0 = NEG, a1 = NEG, b0 = NEG, b1 = NEG;

    int e = 0;
    for (; e + 1 < deg; e += 2) {
        int s0 = __ldg(&lst[e]);          // premultiplied src*32
        int s1 = __ldg(&lst[e + 1]);
        uint2 v0 = __ldg(&C2[(size_t)(uint32_t)(s0 + lane)]);
        uint2 v1 = __ldg(&C2[(size_t)(uint32_t)(s1 + lane)]);
        a0 = hmax2u(a0, v0.x); a1 = hmax2u(a1, v0.y);
        b0 = hmax2u(b0, v1.x); b1 = hmax2u(b1, v1.y);
    }
    if (e < deg) {
        int s0 = __ldg(&lst[e]);
        uint2 v0 = __ldg(&C2[(size_t)(uint32_t)(s0 + lane)]);
        a0 = hmax2u(a0, v0.x); a1 = hmax2u(a1, v0.y);
    }
    a0 = hmax2u(a0, b0);
    a1 = hmax2u(a1, b1);

    float2 m01 = __half22float2(*(__half2*)&a0);
    float2 m23 = __half22float2(*(__half2*)&a1);
    float2 d01 = __half22float2(*(__half2*)&dv.x);
    float2 d23 = __half22float2(*(__half2*)&dv.y);

    float4 o;
    o.x = fmaxf(0.f, d01.x + m01.x);
    o.y = fmaxf(0.f, d01.y + m01.y);
    o.z = fmaxf(0.f, d23.x + m23.x);
    o.w = fmaxf(0.f, d23.y + m23.y);

    if (layer == 3) {
        ((float4*)dout)[(size_t)gw * 32 + lane] = o;
        if (lane == 0) g_cur[gw] = 0;     // re-arm bucket counters for next run
    } else {
        __nv_bfloat16 h0 = __float2bfloat16(o.x), h1 = __float2bfloat16(o.y);
        __nv_bfloat16 h2 = __float2bfloat16(o.z), h3 = __float2bfloat16(o.w);
        __nv_bfloat162 hp0(h0, h1), hp1(h2, h3);
        __nv_bfloat162 lp0(
            __float2bfloat16(o.x - __bfloat162float(h0)),
            __float2bfloat16(o.y - __bfloat162float(h1)));
        __nv_bfloat162 lp1(
            __float2bfloat16(o.z - __bfloat162float(h2)),
            __float2bfloat16(o.w - __bfloat162float(h3)));
        uint2 hv, lv;
        hv.x = *(uint32_t*)&hp0; hv.y = *(uint32_t*)&hp1;
        lv.x = *(uint32_t*)&lp0; lv.y = *(uint32_t*)&lp1;
        *(uint2*)(g_Xh + (size_t)gw * FEAT + lane * 4) = hv;
        *(uint2*)(g_Xl + (size_t)gw * FEAT + lane * 4) = lv;
    }
}

// ---------------- launch ----------------------------------------------------
extern "C" void kernel_launch(void* const* d_in, const int* in_sizes, int n_in,
                              void* d_out, int out_size) {
    const float* feats = (const float*)d_in[0];
    const int*   src   = (const int*)d_in[1];
    const int*   dst   = (const int*)d_in[2];
    const float* tw    = (const float*)d_in[3];
    const float* tb    = (const float*)d_in[4];
    const float* pw    = (const float*)d_in[5];
    const float* pb    = (const float*)d_in[6];

    int n = in_sizes[0] / FEAT;
    int e = in_sizes[1];
    if (n > MAXN) n = MAXN;
    if (e > MAXE) e = MAXE;

    static int smem_set = 0;
    if (!smem_set) {
        cudaFuncSetAttribute(gemm_mma_kernel,
                             cudaFuncAttributeMaxDynamicSharedMemorySize, GEMM_SMEM);
        smem_set = 1;
    }

    // fused setup: X/W decompose + bucket scatter (g_cur pre-zeroed)
    setup_kernel<<<(n * FEAT + 255) / 256, 256>>>(feats, tw, pw, src, dst, n, e);

    int gemm_gx = (n + 127) / 128;
    int warp_blocks = (n * 32 + 255) / 256;

    for (int l = 0; l < 4; l++) {
        gemm_mma_kernel<<<gemm_gx, 512, GEMM_SMEM>>>(l, tb + l * FEAT, pb + l * FEAT, n);
        gather_kernel<<<warp_blocks, 256>>>((float*)d_out, l, n);
    }
}

// round 11
// speedup vs baseline: 1.6491x; 1.3856x over previous
#include <cuda_runtime.h>
#include <cuda_fp16.h>
#include <cstdint>
#include <float.h>

#define FEAT 128
#define MAXN 50000
#define MAXE 600000
#define CAP 96

// ---------------- scratch -------------------------------------------------
__device__ __half g_Ch[MAXN * FEAT];      // theta(x) fp16 (gather reads)
__device__ __half g_Dh[MAXN * FEAT];      // phi - theta + (tb+pb), fp16
__device__ __half g_Xf[MAXN * FEAT];      // current X, fp16
__device__ __half g_Wf[4 * 256 * 128];    // [l][row<128:theta else phi][k]
__device__ int g_cur[MAXN];   // bucket fill count == degree (zero-init at load;
                              // re-zeroed by gather layer 3 for the next run)
__device__ int g_csr[MAXN * CAP];         // premultiplied src*32, bucketed by dst

// ------- fused setup: convert X and W to fp16 + bucket scatter --------------
__global__ void setup_kernel(const float* __restrict__ x,
                             const float* __restrict__ tw,
                             const float* __restrict__ pw,
                             const int* __restrict__ src,
                             const int* __restrict__ dst,
                             int n, int e) {
    int i = blockIdx.x * blockDim.x + threadIdx.x;
    if (i < e) {
        int d = dst[i];
        int p = atomicAdd(&g_cur[d], 1);
        g_csr[d * CAP + p] = src[i] * 32;   // premultiplied uint2-row index
    }
    if (i < 4 * 256 * 128) {
        int l = i >> 15;
        int r = (i >> 7) & 255;
        int k = i & 127;
        const float* W = (r < 128) ? tw : pw;
        g_Wf[i] = __float2half_rn(W[(size_t)l * FEAT * FEAT + (size_t)(r & 127) * FEAT + k]);
    }
    if (i < n * FEAT) {
        g_Xf[i] = __float2half_rn(x[i]);
    }
}

// ---------------- mma.sync fp16 GEMM, 4-stage full prefetch -----------------
// K = 128, 4 chunks of K32. All chunks issued upfront.
#define NKC 4
#define STAGE_BYTES 30720
#define STAGE_B_OFF 10240
#define GEMM_SMEM (4 * STAGE_BYTES)

__device__ __forceinline__ uint32_t smem_u32(const void* p) {
    uint32_t a;
    asm("{ .reg .u64 t; cvta.to.shared.u64 t, %1; cvt.u32.u64 %0, t; }" : "=r"(a) : "l"(p));
    return a;
}
__device__ __forceinline__ uint64_t gmem_u64(const void* p) {
    uint64_t a;
    asm("cvta.to.global.u64 %0, %1;" : "=l"(a) : "l"(p));
    return a;
}
#define CP_ASYNC16(dst, src, sz)                                             \
    asm volatile("cp.async.cg.shared.global [%0], [%1], 16, %2;"             \
                 :: "r"(dst), "l"(src), "r"(sz) : "memory")
#define CP_COMMIT() asm volatile("cp.async.commit_group;" ::: "memory")
#define CP_WAITN(nn) asm volatile("cp.async.wait_group %0;" :: "n"(nn) : "memory")

#define LDMX4(r0, r1, r2, r3, addr)                                          \
    asm volatile("ldmatrix.sync.aligned.m8n8.x4.shared.b16 {%0,%1,%2,%3}, [%4];" \
                 : "=r"(r0), "=r"(r1), "=r"(r2), "=r"(r3) : "r"(addr))
#define MMA16816F(d, a0, a1, a2, a3, b0, b1)                                 \
    asm volatile("mma.sync.aligned.m16n8k16.row.col.f32.f16.f16.f32 "        \
                 "{%0,%1,%2,%3},{%4,%5,%6,%7},{%8,%9},{%0,%1,%2,%3};"        \
                 : "+f"((d)[0]), "+f"((d)[1]), "+f"((d)[2]), "+f"((d)[3])    \
                 : "r"(a0), "r"(a1), "r"(a2), "r"(a3), "r"(b0), "r"(b1))

__global__ void __launch_bounds__(512, 1)
gemm_mma_kernel(int layer, const float* __restrict__ tb,
                const float* __restrict__ pb, int n) {
    extern __shared__ __half sm[];
    uint32_t smb = smem_u32(sm);
    int t = threadIdx.x, lane = t & 31, wid = t >> 5;
    int m0 = blockIdx.x * 128;

    uint64_t Wg = gmem_u64(g_Wf + (size_t)layer * 32768);
    uint64_t Xg = gmem_u64(g_Xf);

    int warp_m = wid & 3;
    int warp_n = wid >> 2;

    int arow = t >> 2, aq = t & 3;
    int gr = m0 + arow;
    uint32_t a_ok = (gr < n) ? 16u : 0u;
    uint32_t a_dst_off = (uint32_t)(arow * 80 + aq * 16);
    uint64_t a_src_off = ((uint64_t)(uint32_t)gr * FEAT + aq * 8) * 2;
    int i0 = t, i1 = t + 512;
    uint32_t b_dst0 = (uint32_t)(STAGE_B_OFF + (i0 >> 2) * 80 + (i0 & 3) * 16);
    uint32_t b_dst1 = (uint32_t)(STAGE_B_OFF + (i1 >> 2) * 80 + (i1 & 3) * 16);
    uint64_t b_src0 = ((uint64_t)(i0 >> 2) * 128 + (i0 & 3) * 8) * 2;
    uint64_t b_src1 = ((uint64_t)(i1 >> 2) * 128 + (i1 & 3) * 8) * 2;

    // issue ALL 4 chunks upfront
    #pragma unroll
    for (int kc = 0; kc < NKC; kc++) {
        uint32_t st = smb + (uint32_t)kc * STAGE_BYTES;
        uint64_t kb = (uint64_t)(kc * 32) * 2;
        CP_ASYNC16(st + a_dst_off, Xg + a_src_off + kb, a_ok);
        CP_ASYNC16(st + b_dst0, Wg + b_src0 + kb, 16u);
        CP_ASYNC16(st + b_dst1, Wg + b_src1 + kb, 16u);
        CP_COMMIT();
    }

    float accT[2][4][4], accP[2][4][4];
    #pragma unroll
    for (int mt = 0; mt < 2; mt++)
        #pragma unroll
        for (int nt = 0; nt < 4; nt++)
            #pragma unroll
            for (int r = 0; r < 4; r++) { accT[mt][nt][r] = 0.f; accP[mt][nt][r] = 0.f; }

    int lr  = (lane & 7) + ((lane >> 3) & 1) * 8;
    int lk8 = (lane >> 4) * 8;
    int bg  = lane >> 3;
    int br_ = (lane & 7) + ((bg >> 1) & 1) * 8;
    int bk8 = (bg & 1) * 8;

    #pragma unroll
    for (int kc = 0; kc < NKC; kc++) {
        if (kc == 0)      { CP_WAITN(3); }
        else if (kc == 1) { CP_WAITN(2); }
        else if (kc == 2) { CP_WAITN(1); }
        else              { CP_WAITN(0); }
        __syncthreads();

        uint32_t stA = smb + (uint32_t)kc * STAGE_BYTES;
        uint32_t stB = stA + STAGE_B_OFF;

        #pragma unroll
        for (int ks = 0; ks < 2; ks++) {
            int k = ks * 16;
            uint32_t aF[2][4];
            #pragma unroll
            for (int mt = 0; mt < 2; mt++) {
                uint32_t ad = stA + (uint32_t)((warp_m * 32 + mt * 16 + lr) * 80 + (k + lk8) * 2);
                LDMX4(aF[mt][0], aF[mt][1], aF[mt][2], aF[mt][3], ad);
            }
            {
                uint32_t bt[4][2];
                #pragma unroll
                for (int nh = 0; nh < 2; nh++) {
                    uint32_t bd = stB + (uint32_t)((warp_n * 32 + nh * 16 + br_) * 80 + (k + bk8) * 2);
                    LDMX4(bt[nh * 2][0], bt[nh * 2][1], bt[nh * 2 + 1][0], bt[nh * 2 + 1][1], bd);
                }
                #pragma unroll
                for (int mt = 0; mt < 2; mt++)
                    #pragma unroll
                    for (int nt = 0; nt < 4; nt++)
                        MMA16816F(accT[mt][nt], aF[mt][0], aF[mt][1], aF[mt][2], aF[mt][3],
                                  bt[nt][0], bt[nt][1]);
            }
            {
                uint32_t bp[4][2];
                #pragma unroll
                for (int nh = 0; nh < 2; nh++) {
                    uint32_t bd = stB + (uint32_t)((128 + warp_n * 32 + nh * 16 + br_) * 80 + (k + bk8) * 2);
                    LDMX4(bp[nh * 2][0], bp[nh * 2][1], bp[nh * 2 + 1][0], bp[nh * 2 + 1][1], bd);
                }
                #pragma unroll
                for (int mt = 0; mt < 2; mt++)
                    #pragma unroll
                    for (int nt = 0; nt < 4; nt++)
                        MMA16816F(accP[mt][nt], aF[mt][0], aF[mt][1], aF[mt][2], aF[mt][3],
                                  bp[nt][0], bp[nt][1]);
            }
        }
    }

    // epilogue: g_Ch = fp16(theta); g_Dh = fp16(phi - theta + (tb+pb))
    #pragma unroll
    for (int mt = 0; mt < 2; mt++) {
        #pragma unroll
        for (int nt = 0; nt < 4; nt++) {
            int f = warp_n * 32 + nt * 8 + (lane & 3) * 2;
            float bias0 = __ldg(&tb[f]) + __ldg(&pb[f]);
            float bias1 = __ldg(&tb[f + 1]) + __ldg(&pb[f + 1]);
            int m = m0 + warp_m * 32 + mt * 16 + (lane >> 2);
            float* c = accT[mt][nt];
            float* p = accP[mt][nt];
            if (m < n) {
                *(__half2*)(g_Ch + (size_t)m * FEAT + f) = __floats2half2_rn(c[0], c[1]);
                *(__half2*)(g_Dh + (size_t)m * FEAT + f) =
                    __floats2half2_rn(p[0] - c[0] + bias0, p[1] - c[1] + bias1);
            }
            if (m + 8 < n) {
                *(__half2*)(g_Ch + (size_t)(m + 8) * FEAT + f) = __floats2half2_rn(c[2], c[3]);
                *(__half2*)(g_Dh + (size_t)(m + 8) * FEAT + f) =
                    __floats2half2_rn(p[2] - c[2] + bias0, p[3] - c[3] + bias1);
            }
        }
    }
}

// ---------------- gather-max: 1 warp/node, uint2, MLP=2 --------------------
__device__ __forceinline__ uint32_t hmax2u(uint32_t x, uint32_t y) {
    __half2 r = __hmax2(*(__half2*)&x, *(__half2*)&y);
    return *(uint32_t*)&r;
}

__global__ void gather_kernel(float* __restrict__ dout, int layer, int n) {
    int gw = (blockIdx.x * blockDim.x + threadIdx.x) >> 5;
    int lane = threadIdx.x & 31;
    if (gw >= n) return;

    int deg = g_cur[gw];
    const int* lst = g_csr + gw * CAP;
    const uint2* C2 = (const uint2*)g_Ch;

    // hoisted D load (independent of edge loop)
    uint2 dv = __ldg(&((const uint2*)g_Dh)[(size_t)gw * 32 + lane]);

    const uint32_t NEG = 0xFBFFFBFFu;  // -65504 x2
    uint32_t a0 = NEG, a1 = NEG, b0 = NEG, b1 = NEG;

    int e = 0;
    for (; e + 1 < deg; e += 2) {
        int s0 = __ldg(&lst[e]);          // premultiplied src*32
        int s1 = __ldg(&lst[e + 1]);
        uint2 v0 = __ldg(&C2[(size_t)(uint32_t)(s0 + lane)]);
        uint2 v1 = __ldg(&C2[(size_t)(uint32_t)(s1 + lane)]);
        a0 = hmax2u(a0, v0.x); a1 = hmax2u(a1, v0.y);
        b0 = hmax2u(b0, v1.x); b1 = hmax2u(b1, v1.y);
    }
    if (e < deg) {
        int s0 = __ldg(&lst[e]);
        uint2 v0 = __ldg(&C2[(size_t)(uint32_t)(s0 + lane)]);
        a0 = hmax2u(a0, v0.x); a1 = hmax2u(a1, v0.y);
    }
    a0 = hmax2u(a0, b0);
    a1 = hmax2u(a1, b1);

    float2 m01 = __half22float2(*(__half2*)&a0);
    float2 m23 = __half22float2(*(__half2*)&a1);
    float2 d01 = __half22float2(*(__half2*)&dv.x);
    float2 d23 = __half22float2(*(__half2*)&dv.y);

    float4 o;
    o.x = fmaxf(0.f, d01.x + m01.x);
    o.y = fmaxf(0.f, d01.y + m01.y);
    o.z = fmaxf(0.f, d23.x + m23.x);
    o.w = fmaxf(0.f, d23.y + m23.y);

    if (layer == 3) {
        ((float4*)dout)[(size_t)gw * 32 + lane] = o;
        if (lane == 0) g_cur[gw] = 0;     // re-arm bucket counters for next run
    } else {
        __half2 p0 = __floats2half2_rn(o.x, o.y);
        __half2 p1 = __floats2half2_rn(o.z, o.w);
        uint2 xv;
        xv.x = *(uint32_t*)&p0;
        xv.y = *(uint32_t*)&p1;
        *(uint2*)(g_Xf + (size_t)gw * FEAT + lane * 4) = xv;
    }
}

// ---------------- launch ----------------------------------------------------
extern "C" void kernel_launch(void* const* d_in, const int* in_sizes, int n_in,
                              void* d_out, int out_size) {
    const float* feats = (const float*)d_in[0];
    const int*   src   = (const int*)d_in[1];
    const int*   dst   = (const int*)d_in[2];
    const float* tw    = (const float*)d_in[3];
    const float* tb    = (const float*)d_in[4];
    const float* pw    = (const float*)d_in[5];
    const float* pb    = (const float*)d_in[6];

    int n = in_sizes[0] / FEAT;
    int e = in_sizes[1];
    if (n > MAXN) n = MAXN;
    if (e > MAXE) e = MAXE;

    static int smem_set = 0;
    if (!smem_set) {
        cudaFuncSetAttribute(gemm_mma_kernel,
                             cudaFuncAttributeMaxDynamicSharedMemorySize, GEMM_SMEM);
        smem_set = 1;
    }

    // fused setup: X/W fp16 convert + bucket scatter (g_cur pre-zeroed)
    setup_kernel<<<(n * FEAT + 255) / 256, 256>>>(feats, tw, pw, src, dst, n, e);

    int gemm_gx = (n + 127) / 128;
    int warp_blocks = (n * 32 + 255) / 256;

    for (int l = 0; l < 4; l++) {
        gemm_mma_kernel<<<gemm_gx, 512, GEMM_SMEM>>>(l, tb + l * FEAT, pb + l * FEAT, n);
        gather_kernel<<<warp_blocks, 256>>>((float*)d_out, l, n);
    }
}